// round 1
// baseline (speedup 1.0000x reference)
#include <cuda_runtime.h>
#include <cuda_bf16.h>
#include <cstdint>

#define D_MODEL 384
#define NUM_B   8
#define SEQ     2048
#define NUM_H   8
#define DH      48
#define MROWS   (NUM_B * SEQ)          // 16384

// ---------------- scratch (no allocs allowed) ----------------
__device__ float g_q[MROWS * D_MODEL];
__device__ float g_k[MROWS * D_MODEL];
__device__ float g_v[MROWS * D_MODEL];

// ---------------- projection GEMM: Y = X @ W + b -------------
// M=16384, N=K=384. BM=BN=64, BK=16, 256 threads, 4x4 micro-tile.
__global__ __launch_bounds__(256) void proj_kernel(
    const float* __restrict__ X, const float* __restrict__ W,
    const float* __restrict__ bias, float* __restrict__ Y)
{
    __shared__ float As[16][65];   // [k][m], padded
    __shared__ float Bs[16][68];   // [k][n], padded

    const int tid = threadIdx.x;
    const int tx  = tid & 15;      // n direction
    const int ty  = tid >> 4;      // m direction
    const int m0  = blockIdx.y * 64;
    const int n0  = blockIdx.x * 64;

    float4 acc[4];
    #pragma unroll
    for (int i = 0; i < 4; ++i) acc[i] = make_float4(0.f, 0.f, 0.f, 0.f);

    for (int k0 = 0; k0 < D_MODEL; k0 += 16) {
        // X tile 64x16 -> As transposed
        {
            int idx = tid * 4;
            int m = idx >> 4;
            int kk = idx & 15;
            float4 xv = *(const float4*)(X + (size_t)(m0 + m) * D_MODEL + k0 + kk);
            As[kk + 0][m] = xv.x; As[kk + 1][m] = xv.y;
            As[kk + 2][m] = xv.z; As[kk + 3][m] = xv.w;
        }
        // W tile 16x64 -> Bs
        {
            int idx = tid * 4;
            int kk = idx >> 6;
            int n  = idx & 63;
            *(float4*)&Bs[kk][n] = *(const float4*)(W + (size_t)(k0 + kk) * D_MODEL + n0 + n);
        }
        __syncthreads();
        #pragma unroll
        for (int kk = 0; kk < 16; ++kk) {
            float a0 = As[kk][ty * 4 + 0];
            float a1 = As[kk][ty * 4 + 1];
            float a2 = As[kk][ty * 4 + 2];
            float a3 = As[kk][ty * 4 + 3];
            float4 bv = *(float4*)&Bs[kk][tx * 4];
            acc[0].x += a0 * bv.x; acc[0].y += a0 * bv.y; acc[0].z += a0 * bv.z; acc[0].w += a0 * bv.w;
            acc[1].x += a1 * bv.x; acc[1].y += a1 * bv.y; acc[1].z += a1 * bv.z; acc[1].w += a1 * bv.w;
            acc[2].x += a2 * bv.x; acc[2].y += a2 * bv.y; acc[2].z += a2 * bv.z; acc[2].w += a2 * bv.w;
            acc[3].x += a3 * bv.x; acc[3].y += a3 * bv.y; acc[3].z += a3 * bv.z; acc[3].w += a3 * bv.w;
        }
        __syncthreads();
    }

    float4 bv = *(const float4*)(bias + n0 + tx * 4);
    #pragma unroll
    for (int i = 0; i < 4; ++i) {
        float4 o;
        o.x = acc[i].x + bv.x; o.y = acc[i].y + bv.y;
        o.z = acc[i].z + bv.z; o.w = acc[i].w + bv.w;
        *(float4*)(Y + (size_t)(m0 + ty * 4 + i) * D_MODEL + n0 + tx * 4) = o;
    }
}

// ---------------- attention kernel ---------------------------
// grid (SEQ/8, H, B), 256 threads = 8 warps, warp-per-query-row.
// Scores in dynamic SMEM [8][2048]; K/V chunked 128 keys (stride 52 floats).
#define CHUNK 128
#define KSTR  52
#define NCHUNK (SEQ / CHUNK)
#define SMEM_BYTES ((8 * SEQ + CHUNK * KSTR) * 4)

__global__ __launch_bounds__(256) void attn_kernel(
    float* __restrict__ ctx, float* __restrict__ attn)
{
    extern __shared__ float sm[];
    float* ssc = sm;                   // [8][SEQ]
    float* sk  = sm + 8 * SEQ;         // [CHUNK][KSTR]

    const int b    = blockIdx.z;
    const int h    = blockIdx.y;
    const int warp = threadIdx.x >> 5;
    const int lane = threadIdx.x & 31;
    const int qrow = blockIdx.x * 8 + warp;

    const float* kbase = g_k + (size_t)b * SEQ * D_MODEL + h * DH;
    const float* vbase = g_v + (size_t)b * SEQ * D_MODEL + h * DH;

    // q row into registers (12 float4 = 48 floats)
    float4 q[12];
    {
        const float* qp = g_q + (size_t)(b * SEQ + qrow) * D_MODEL + h * DH;
        #pragma unroll
        for (int i = 0; i < 12; ++i) q[i] = *(const float4*)(qp + i * 4);
    }
    const float scale = 0.14433756729740644f;   // 1/sqrt(48)
    float* srow = ssc + warp * SEQ;

    // ---- phase 1: scores ----
    for (int c = 0; c < NCHUNK; ++c) {
        __syncthreads();                 // previous chunk consumed
        for (int t = threadIdx.x; t < CHUNK * 12; t += 256) {
            int key = t / 12, d4 = t - key * 12;
            float4 kv = *(const float4*)(kbase + (size_t)(c * CHUNK + key) * D_MODEL + d4 * 4);
            *(float4*)&sk[key * KSTR + d4 * 4] = kv;
        }
        __syncthreads();
        #pragma unroll
        for (int j = 0; j < 4; ++j) {
            int kl = j * 32 + lane;
            const float* kp = &sk[kl * KSTR];
            float acc = 0.f;
            #pragma unroll
            for (int i = 0; i < 12; ++i) {
                float4 kv = *(const float4*)(kp + i * 4);
                acc += q[i].x * kv.x + q[i].y * kv.y + q[i].z * kv.z + q[i].w * kv.w;
            }
            srow[c * CHUNK + kl] = acc * scale;
        }
    }
    __syncwarp();

    // ---- softmax over this warp's row (each lane touches only its own keys) ----
    float m = -1e30f;
    for (int i = lane; i < SEQ; i += 32) m = fmaxf(m, srow[i]);
    #pragma unroll
    for (int o = 16; o; o >>= 1) m = fmaxf(m, __shfl_xor_sync(0xffffffffu, m, o));
    float sum = 0.f;
    for (int i = lane; i < SEQ; i += 32) {
        float p = __expf(srow[i] - m);
        srow[i] = p;
        sum += p;
    }
    #pragma unroll
    for (int o = 16; o; o >>= 1) sum += __shfl_xor_sync(0xffffffffu, sum, o);
    const float inv = 1.f / sum;

    // write attention row: layout (H*B, Sq, Sk)
    float* ap = attn + ((size_t)(h * NUM_B + b) * SEQ + qrow) * SEQ;
    for (int i = lane; i < SEQ; i += 32) {
        float p = srow[i] * inv;
        srow[i] = p;
        ap[i] = p;
    }
    __syncwarp();

    // ---- phase 2: context = P @ V ----
    float4 a4[12];
    #pragma unroll
    for (int i = 0; i < 12; ++i) a4[i] = make_float4(0.f, 0.f, 0.f, 0.f);

    for (int c = 0; c < NCHUNK; ++c) {
        __syncthreads();
        for (int t = threadIdx.x; t < CHUNK * 12; t += 256) {
            int key = t / 12, d4 = t - key * 12;
            float4 vv = *(const float4*)(vbase + (size_t)(c * CHUNK + key) * D_MODEL + d4 * 4);
            *(float4*)&sk[key * KSTR + d4 * 4] = vv;
        }
        __syncthreads();
        #pragma unroll
        for (int j = 0; j < 4; ++j) {
            int kl = j * 32 + lane;
            float p = srow[c * CHUNK + kl];
            const float* vp = &sk[kl * KSTR];
            #pragma unroll
            for (int i = 0; i < 12; ++i) {
                float4 vv = *(const float4*)(vp + i * 4);
                a4[i].x += p * vv.x; a4[i].y += p * vv.y;
                a4[i].z += p * vv.z; a4[i].w += p * vv.w;
            }
        }
    }

    // cross-lane reduce all 48 accumulators (butterfly; every lane ends with totals)
    #pragma unroll
    for (int i = 0; i < 12; ++i) {
        #pragma unroll
        for (int o = 16; o; o >>= 1) {
            a4[i].x += __shfl_xor_sync(0xffffffffu, a4[i].x, o);
            a4[i].y += __shfl_xor_sync(0xffffffffu, a4[i].y, o);
            a4[i].z += __shfl_xor_sync(0xffffffffu, a4[i].z, o);
            a4[i].w += __shfl_xor_sync(0xffffffffu, a4[i].w, o);
        }
    }
    if (lane == 0) {
        float* cp = ctx + (size_t)(b * SEQ + qrow) * D_MODEL + h * DH;
        #pragma unroll
        for (int i = 0; i < 12; ++i) *(float4*)(cp + i * 4) = a4[i];
    }
}

// ---------------- launch -------------------------------------
extern "C" void kernel_launch(void* const* d_in, const int* in_sizes, int n_in,
                              void* d_out, int out_size)
{
    const float* query = (const float*)d_in[0];
    const float* key   = (const float*)d_in[1];
    const float* value = (const float*)d_in[2];
    const float* Wq    = (const float*)d_in[3];
    const float* bq    = (const float*)d_in[4];
    const float* Wk    = (const float*)d_in[5];
    const float* bk    = (const float*)d_in[6];
    const float* Wv    = (const float*)d_in[7];
    const float* bv    = (const float*)d_in[8];

    float* out  = (float*)d_out;
    float* ctx  = out;                                   // (B, S, 384)
    float* attn = out + (size_t)MROWS * D_MODEL;         // (H*B, S, S)

    void* pq = nullptr; void* pk = nullptr; void* pv = nullptr;
    cudaGetSymbolAddress(&pq, g_q);
    cudaGetSymbolAddress(&pk, g_k);
    cudaGetSymbolAddress(&pv, g_v);

    cudaFuncSetAttribute(attn_kernel, cudaFuncAttributeMaxDynamicSharedMemorySize, SMEM_BYTES);

    dim3 pgrid(D_MODEL / 64, MROWS / 64);
    proj_kernel<<<pgrid, 256>>>(query, Wq, bq, (float*)pq);
    proj_kernel<<<pgrid, 256>>>(key,   Wk, bk, (float*)pk);
    proj_kernel<<<pgrid, 256>>>(value, Wv, bv, (float*)pv);

    dim3 agrid(SEQ / 8, NUM_H, NUM_B);
    attn_kernel<<<agrid, 256, SMEM_BYTES>>>(ctx, attn);
}

// round 3
// speedup vs baseline: 3.2818x; 3.2818x over previous
#include <cuda_runtime.h>
#include <cuda_bf16.h>
#include <cstdint>

#define D_MODEL 384
#define NUM_B   8
#define SEQ     2048
#define NUM_H   8
#define DH      48
#define MROWS   (NUM_B * SEQ)          // 16384
#define SCALE   0.14433756729740644f   // 1/sqrt(48)

// ---------------- scratch (no allocs allowed) ----------------
__device__ float g_q[MROWS * D_MODEL];
__device__ float g_k[MROWS * D_MODEL];
__device__ float g_v[MROWS * D_MODEL];
__device__ float g_m[NUM_B * NUM_H * SEQ];   // per-row running max
__device__ float g_s[NUM_B * NUM_H * SEQ];   // per-row exp-sum

// ---------------- tf32 helpers -------------------------------
__device__ __forceinline__ uint32_t f2tf(float f) {
    uint32_t u;
    asm("cvt.rna.tf32.f32 %0, %1;" : "=r"(u) : "f"(f));
    return u;
}
__device__ __forceinline__ uint4 f4tf(float4 v) {
    return make_uint4(f2tf(v.x), f2tf(v.y), f2tf(v.z), f2tf(v.w));
}
// D(16x8) += A(16x8,row) * B(8x8,col). a: per-thread 4 regs, b: 2 regs.
__device__ __forceinline__ void mma_tf32(float4& d, const uint32_t a[4],
                                         uint32_t b0, uint32_t b1) {
    asm volatile(
        "mma.sync.aligned.m16n8k8.row.col.f32.tf32.tf32.f32 "
        "{%0,%1,%2,%3},{%4,%5,%6,%7},{%8,%9},{%0,%1,%2,%3};"
        : "+f"(d.x), "+f"(d.y), "+f"(d.z), "+f"(d.w)
        : "r"(a[0]), "r"(a[1]), "r"(a[2]), "r"(a[3]), "r"(b0), "r"(b1));
}

// ---------------- projection GEMM (tf32 MMA) -----------------
// Y = X @ W + b.  M=16384, N=K=384. Block 128x128, 8 warps, warp = 16 rows.
#define XSTR 36    // a-frag pattern (8 rows x 4 cols): 36 mod 32 = 4 -> conflict-free
#define WSTR 136   // b-frag pattern (4 rows x 8 cols): 136 mod 32 = 8 -> conflict-free
__global__ __launch_bounds__(256, 2) void proj_tc(
    const float* __restrict__ X, const float* __restrict__ W,
    const float* __restrict__ bias, float* __restrict__ Y)
{
    __shared__ uint32_t Xs[128 * XSTR];
    __shared__ uint32_t Ws[32 * WSTR];
    const int n0 = blockIdx.x * 128, m0 = blockIdx.y * 128;
    const int tid = threadIdx.x;
    const int w = tid >> 5, lane = tid & 31, g = lane >> 2, t = lane & 3;
    const int row = 16 * w + g;

    float4 acc[16];
    #pragma unroll
    for (int i = 0; i < 16; ++i) acc[i] = make_float4(0.f, 0.f, 0.f, 0.f);

    for (int kc = 0; kc < 12; ++kc) {
        __syncthreads();
        for (int i = tid; i < 128 * 8; i += 256) {          // X tile 128x32
            int r = i >> 3, c4 = i & 7;
            float4 v = *(const float4*)(X + (size_t)(m0 + r) * D_MODEL + kc * 32 + c4 * 4);
            *(uint4*)(Xs + r * XSTR + c4 * 4) = f4tf(v);
        }
        for (int i = tid; i < 32 * 32; i += 256) {          // W tile 32x128
            int r = i >> 5, c4 = i & 31;
            float4 v = *(const float4*)(W + (size_t)(kc * 32 + r) * D_MODEL + n0 + c4 * 4);
            *(uint4*)(Ws + r * WSTR + c4 * 4) = f4tf(v);
        }
        __syncthreads();
        #pragma unroll
        for (int kk = 0; kk < 4; ++kk) {
            uint32_t a[4];
            a[0] = Xs[row * XSTR + kk * 8 + t];
            a[1] = Xs[(row + 8) * XSTR + kk * 8 + t];
            a[2] = Xs[row * XSTR + kk * 8 + t + 4];
            a[3] = Xs[(row + 8) * XSTR + kk * 8 + t + 4];
            #pragma unroll
            for (int ns = 0; ns < 16; ++ns) {
                uint32_t b0 = Ws[(kk * 8 + t) * WSTR + ns * 8 + g];
                uint32_t b1 = Ws[(kk * 8 + t + 4) * WSTR + ns * 8 + g];
                mma_tf32(acc[ns], a, b0, b1);
            }
        }
    }
    #pragma unroll
    for (int ns = 0; ns < 16; ++ns) {
        int c = n0 + ns * 8 + 2 * t;
        float bv0 = bias[c], bv1 = bias[c + 1];
        *(float2*)(Y + (size_t)(m0 + row) * D_MODEL + c) =
            make_float2(acc[ns].x + bv0, acc[ns].y + bv1);
        *(float2*)(Y + (size_t)(m0 + row + 8) * D_MODEL + c) =
            make_float2(acc[ns].z + bv0, acc[ns].w + bv1);
    }
}

// ---------------- kernel A: raw logits + softmax stats -------
// grid (16, H, B): 128 q-rows per CTA, loop 16 chunks of 128 keys.
// Writes raw scaled logits into attn buffer; tracks running (m, sum) per row.
#define QKSTR 52   // both a-frag (8rx4c: 52%32=20 ok) and b-frag (8rx4c) patterns conflict-free
__global__ __launch_bounds__(256, 2) void scores_kernel(float* __restrict__ attn)
{
    extern __shared__ uint32_t smA[];
    uint32_t* Qs = smA;                 // [128][52]
    uint32_t* Ks = smA + 128 * QKSTR;   // [128][52]
    const int b = blockIdx.z, h = blockIdx.y;
    const int qbase = blockIdx.x * 128;
    const int tid = threadIdx.x;
    const int w = tid >> 5, lane = tid & 31, g = lane >> 2, t = lane & 3;
    const int row = 16 * w + g;

    const float* qp = g_q + ((size_t)(b * SEQ + qbase)) * D_MODEL + h * DH;
    for (int i = tid; i < 128 * 12; i += 256) {
        int r = i / 12, c = i % 12;
        float4 v = *(const float4*)(qp + (size_t)r * D_MODEL + c * 4);
        *(uint4*)(Qs + r * QKSTR + c * 4) = f4tf(v);
    }
    const float* kp = g_k + (size_t)b * SEQ * D_MODEL + h * DH;
    float* arow = attn + ((size_t)(h * NUM_B + b) * SEQ + qbase) * SEQ;

    float m0 = -1e30f, m1 = -1e30f, s0 = 0.f, s1 = 0.f;

    for (int ch = 0; ch < 16; ++ch) {
        __syncthreads();
        for (int i = tid; i < 128 * 12; i += 256) {
            int r = i / 12, c = i % 12;
            float4 v = *(const float4*)(kp + (size_t)(ch * 128 + r) * D_MODEL + c * 4);
            *(uint4*)(Ks + r * QKSTR + c * 4) = f4tf(v);
        }
        __syncthreads();
        uint32_t a[6][4];
        #pragma unroll
        for (int kk = 0; kk < 6; ++kk) {
            a[kk][0] = Qs[row * QKSTR + kk * 8 + t];
            a[kk][1] = Qs[(row + 8) * QKSTR + kk * 8 + t];
            a[kk][2] = Qs[row * QKSTR + kk * 8 + t + 4];
            a[kk][3] = Qs[(row + 8) * QKSTR + kk * 8 + t + 4];
        }
        float4 acc[16];
        #pragma unroll
        for (int ns = 0; ns < 16; ++ns) acc[ns] = make_float4(0.f, 0.f, 0.f, 0.f);
        #pragma unroll
        for (int ns = 0; ns < 16; ++ns) {
            #pragma unroll
            for (int kk = 0; kk < 6; ++kk) {
                uint32_t b0 = Ks[(ns * 8 + g) * QKSTR + kk * 8 + t];
                uint32_t b1 = Ks[(ns * 8 + g) * QKSTR + kk * 8 + t + 4];
                mma_tf32(acc[ns], a[kk], b0, b1);
            }
        }
        // scale + chunk row-max (rows: row -> .x/.y ; row+8 -> .z/.w)
        float cm0 = -1e30f, cm1 = -1e30f;
        #pragma unroll
        for (int ns = 0; ns < 16; ++ns) {
            acc[ns].x *= SCALE; acc[ns].y *= SCALE;
            acc[ns].z *= SCALE; acc[ns].w *= SCALE;
            cm0 = fmaxf(cm0, fmaxf(acc[ns].x, acc[ns].y));
            cm1 = fmaxf(cm1, fmaxf(acc[ns].z, acc[ns].w));
        }
        cm0 = fmaxf(cm0, __shfl_xor_sync(0xffffffffu, cm0, 1));
        cm0 = fmaxf(cm0, __shfl_xor_sync(0xffffffffu, cm0, 2));
        cm1 = fmaxf(cm1, __shfl_xor_sync(0xffffffffu, cm1, 1));
        cm1 = fmaxf(cm1, __shfl_xor_sync(0xffffffffu, cm1, 2));
        float nm0 = fmaxf(m0, cm0), nm1 = fmaxf(m1, cm1);
        float e0 = 0.f, e1 = 0.f;
        #pragma unroll
        for (int ns = 0; ns < 16; ++ns) {
            e0 += __expf(acc[ns].x - nm0) + __expf(acc[ns].y - nm0);
            e1 += __expf(acc[ns].z - nm1) + __expf(acc[ns].w - nm1);
        }
        e0 += __shfl_xor_sync(0xffffffffu, e0, 1);
        e0 += __shfl_xor_sync(0xffffffffu, e0, 2);
        e1 += __shfl_xor_sync(0xffffffffu, e1, 1);
        e1 += __shfl_xor_sync(0xffffffffu, e1, 2);
        s0 = s0 * __expf(m0 - nm0) + e0;  m0 = nm0;
        s1 = s1 * __expf(m1 - nm1) + e1;  m1 = nm1;
        // write raw logits (32B-sector friendly float2 stores)
        float* r0p = arow + (size_t)row * SEQ + ch * 128 + 2 * t;
        float* r1p = r0p + (size_t)8 * SEQ;
        #pragma unroll
        for (int ns = 0; ns < 16; ++ns) {
            *(float2*)(r0p + ns * 8) = make_float2(acc[ns].x, acc[ns].y);
            *(float2*)(r1p + ns * 8) = make_float2(acc[ns].z, acc[ns].w);
        }
    }
    if (t == 0) {
        size_t ridx = (size_t)(b * NUM_H + h) * SEQ + qbase + row;
        g_m[ridx] = m0;     g_s[ridx] = s0;
        g_m[ridx + 8] = m1; g_s[ridx + 8] = s1;
    }
}

// ---------------- kernel B: normalize + context = P @ V ------
#define PSTR 132   // a-frag pattern: 132%32=4 -> conflict-free
#define VSTR 56    // b-frag pattern (4 rows x 8 cols): 56%32=24 -> conflict-free
__global__ __launch_bounds__(256, 2) void context_kernel(
    float* __restrict__ ctx, float* __restrict__ attn)
{
    extern __shared__ uint32_t smB[];
    uint32_t* Ps = smB;                             // [128][132] tf32
    uint32_t* Vs = smB + 128 * PSTR;                // [128][56]  tf32
    float* sm_m = (float*)(smB + 128 * PSTR + 128 * VSTR);  // [128]
    float* sm_i = sm_m + 128;                                // [128]

    const int b = blockIdx.z, h = blockIdx.y;
    const int qbase = blockIdx.x * 128;
    const int tid = threadIdx.x;
    const int w = tid >> 5, lane = tid & 31, g = lane >> 2, t = lane & 3;
    const int row = 16 * w + g;

    if (tid < 128) {
        size_t rbase = (size_t)(b * NUM_H + h) * SEQ + qbase;
        sm_m[tid] = g_m[rbase + tid];
        sm_i[tid] = 1.f / g_s[rbase + tid];
    }
    const float* vp = g_v + (size_t)b * SEQ * D_MODEL + h * DH;
    float* arow = attn + ((size_t)(h * NUM_B + b) * SEQ + qbase) * SEQ;

    float4 acc[6];
    #pragma unroll
    for (int n = 0; n < 6; ++n) acc[n] = make_float4(0.f, 0.f, 0.f, 0.f);

    for (int ch = 0; ch < 16; ++ch) {
        __syncthreads();
        for (int i = tid; i < 128 * 12; i += 256) {          // V chunk 128x48
            int r = i / 12, c = i % 12;
            float4 v = *(const float4*)(vp + (size_t)(ch * 128 + r) * D_MODEL + c * 4);
            *(uint4*)(Vs + r * VSTR + c * 4) = f4tf(v);
        }
        for (int i = tid; i < 128 * 32; i += 256) {          // P chunk 128x128
            int r = i >> 5, c4 = i & 31;
            float* ap = arow + (size_t)r * SEQ + ch * 128 + c4 * 4;
            float4 sv = *(float4*)ap;
            float mm = sm_m[r], iv = sm_i[r];
            float4 p = make_float4(__expf(sv.x - mm) * iv, __expf(sv.y - mm) * iv,
                                   __expf(sv.z - mm) * iv, __expf(sv.w - mm) * iv);
            *(float4*)ap = p;                                 // final attn output
            *(uint4*)(Ps + r * PSTR + c4 * 4) = f4tf(p);
        }
        __syncthreads();
        #pragma unroll
        for (int kk = 0; kk < 16; ++kk) {
            uint32_t a[4];
            a[0] = Ps[row * PSTR + kk * 8 + t];
            a[1] = Ps[(row + 8) * PSTR + kk * 8 + t];
            a[2] = Ps[row * PSTR + kk * 8 + t + 4];
            a[3] = Ps[(row + 8) * PSTR + kk * 8 + t + 4];
            #pragma unroll
            for (int n = 0; n < 6; ++n) {
                uint32_t b0 = Vs[(kk * 8 + t) * VSTR + n * 8 + g];
                uint32_t b1 = Vs[(kk * 8 + t + 4) * VSTR + n * 8 + g];
                mma_tf32(acc[n], a, b0, b1);
            }
        }
    }
    float* cp  = ctx + ((size_t)(b * SEQ + qbase + row)) * D_MODEL + h * DH + 2 * t;
    float* cp2 = cp + (size_t)8 * D_MODEL;
    #pragma unroll
    for (int n = 0; n < 6; ++n) {
        *(float2*)(cp  + n * 8) = make_float2(acc[n].x, acc[n].y);
        *(float2*)(cp2 + n * 8) = make_float2(acc[n].z, acc[n].w);
    }
}

// ---------------- launch -------------------------------------
#define SC_SMEM (2 * 128 * QKSTR * 4)                          // 53248 B
#define CT_SMEM ((128 * PSTR + 128 * VSTR + 256) * 4)          // 97280 B

extern "C" void kernel_launch(void* const* d_in, const int* in_sizes, int n_in,
                              void* d_out, int out_size)
{
    const float* query = (const float*)d_in[0];
    const float* key   = (const float*)d_in[1];
    const float* value = (const float*)d_in[2];
    const float* Wq    = (const float*)d_in[3];
    const float* bq    = (const float*)d_in[4];
    const float* Wk    = (const float*)d_in[5];
    const float* bk    = (const float*)d_in[6];
    const float* Wv    = (const float*)d_in[7];
    const float* bv    = (const float*)d_in[8];

    float* out  = (float*)d_out;
    float* ctx  = out;                                   // (B, S, 384)
    float* attn = out + (size_t)MROWS * D_MODEL;         // (H*B, S, S)

    void* pq = nullptr; void* pk = nullptr; void* pv = nullptr;
    cudaGetSymbolAddress(&pq, g_q);
    cudaGetSymbolAddress(&pk, g_k);
    cudaGetSymbolAddress(&pv, g_v);

    cudaFuncSetAttribute(scores_kernel,  cudaFuncAttributeMaxDynamicSharedMemorySize, SC_SMEM);
    cudaFuncSetAttribute(context_kernel, cudaFuncAttributeMaxDynamicSharedMemorySize, CT_SMEM);

    dim3 pgrid(D_MODEL / 128, MROWS / 128);              // (3, 128)
    proj_tc<<<pgrid, 256>>>(query, Wq, bq, (float*)pq);
    proj_tc<<<pgrid, 256>>>(key,   Wk, bk, (float*)pk);
    proj_tc<<<pgrid, 256>>>(value, Wv, bv, (float*)pv);

    dim3 agrid(SEQ / 128, NUM_H, NUM_B);                 // (16, 8, 8)
    scores_kernel<<<agrid, 256, SC_SMEM>>>(attn);
    context_kernel<<<agrid, 256, CT_SMEM>>>(ctx, attn);
}

// round 4
// speedup vs baseline: 4.7630x; 1.4513x over previous
#include <cuda_runtime.h>
#include <cuda_bf16.h>
#include <cstdint>

#define D_MODEL 384
#define NUM_B   8
#define SEQ     2048
#define NUM_H   8
#define DH      48
#define MROWS   (NUM_B * SEQ)          // 16384
// 1/sqrt(48) * log2(e): fold softmax scale and exp->exp2 conversion
#define SL2E    (0.14433756729740644f * 1.4426950408889634f)

// ---------------- scratch (no allocs allowed) ----------------
__device__ float g_q[MROWS * D_MODEL];
__device__ float g_k[MROWS * D_MODEL];
__device__ float g_v[MROWS * D_MODEL];

// ---------------- tf32 helpers -------------------------------
__device__ __forceinline__ uint32_t f2tf(float f) {
    uint32_t u;
    asm("cvt.rna.tf32.f32 %0, %1;" : "=r"(u) : "f"(f));
    return u;
}
__device__ __forceinline__ uint4 f4tf(float4 v) {
    return make_uint4(f2tf(v.x), f2tf(v.y), f2tf(v.z), f2tf(v.w));
}
// D(16x8) += A(16x8,row) * B(8x8,col).
__device__ __forceinline__ void mma_tf32(float4& d, const uint32_t a[4],
                                         uint32_t b0, uint32_t b1) {
    asm volatile(
        "mma.sync.aligned.m16n8k8.row.col.f32.tf32.tf32.f32 "
        "{%0,%1,%2,%3},{%4,%5,%6,%7},{%8,%9},{%0,%1,%2,%3};"
        : "+f"(d.x), "+f"(d.y), "+f"(d.z), "+f"(d.w)
        : "r"(a[0]), "r"(a[1]), "r"(a[2]), "r"(a[3]), "r"(b0), "r"(b1));
}

// ---------------- projection GEMM (tf32 MMA) -----------------
#define XSTR 36
#define WSTR 136
__global__ __launch_bounds__(256, 2) void proj_tc(
    const float* __restrict__ X, const float* __restrict__ W,
    const float* __restrict__ bias, float* __restrict__ Y)
{
    __shared__ uint32_t Xs[128 * XSTR];
    __shared__ uint32_t Ws[32 * WSTR];
    const int n0 = blockIdx.x * 128, m0 = blockIdx.y * 128;
    const int tid = threadIdx.x;
    const int w = tid >> 5, lane = tid & 31, g = lane >> 2, t = lane & 3;
    const int row = 16 * w + g;

    float4 acc[16];
    #pragma unroll
    for (int i = 0; i < 16; ++i) acc[i] = make_float4(0.f, 0.f, 0.f, 0.f);

    for (int kc = 0; kc < 12; ++kc) {
        __syncthreads();
        for (int i = tid; i < 128 * 8; i += 256) {
            int r = i >> 3, c4 = i & 7;
            float4 v = *(const float4*)(X + (size_t)(m0 + r) * D_MODEL + kc * 32 + c4 * 4);
            *(uint4*)(Xs + r * XSTR + c4 * 4) = f4tf(v);
        }
        for (int i = tid; i < 32 * 32; i += 256) {
            int r = i >> 5, c4 = i & 31;
            float4 v = *(const float4*)(W + (size_t)(kc * 32 + r) * D_MODEL + n0 + c4 * 4);
            *(uint4*)(Ws + r * WSTR + c4 * 4) = f4tf(v);
        }
        __syncthreads();
        #pragma unroll
        for (int kk = 0; kk < 4; ++kk) {
            uint32_t a[4];
            a[0] = Xs[row * XSTR + kk * 8 + t];
            a[1] = Xs[(row + 8) * XSTR + kk * 8 + t];
            a[2] = Xs[row * XSTR + kk * 8 + t + 4];
            a[3] = Xs[(row + 8) * XSTR + kk * 8 + t + 4];
            #pragma unroll
            for (int ns = 0; ns < 16; ++ns) {
                uint32_t b0 = Ws[(kk * 8 + t) * WSTR + ns * 8 + g];
                uint32_t b1 = Ws[(kk * 8 + t + 4) * WSTR + ns * 8 + g];
                mma_tf32(acc[ns], a, b0, b1);
            }
        }
    }
    #pragma unroll
    for (int ns = 0; ns < 16; ++ns) {
        int c = n0 + ns * 8 + 2 * t;
        float bv0 = bias[c], bv1 = bias[c + 1];
        *(float2*)(Y + (size_t)(m0 + row) * D_MODEL + c) =
            make_float2(acc[ns].x + bv0, acc[ns].y + bv1);
        *(float2*)(Y + (size_t)(m0 + row + 8) * D_MODEL + c) =
            make_float2(acc[ns].z + bv0, acc[ns].w + bv1);
    }
}

// ---------------- fused attention ----------------------------
// grid (16, H, B): 128 q-rows per CTA.
// Pass 1: online (m, s) over 16 chunks of 128 keys (Q·K^T MMA, no stores).
// Pass 2: recompute Q·K^T, normalize in regs, write final attn, shuffle P
//         C-frags into A-frags, accumulate context MMA — P never hits smem.
#define KSTR 52    // Q/K tile stride: b-frag lanes g*52+t -> conflict-free
#define VSTR 56    // V tile stride:   b-frag lanes t*56+g -> conflict-free
#define FUSED_SMEM ((128 * KSTR + 128 * VSTR) * 4)   // 55296 B

__global__ __launch_bounds__(256, 2) void fused_attn(
    float* __restrict__ ctx, float* __restrict__ attn)
{
    extern __shared__ uint32_t sm[];
    uint32_t* Ks = sm;                 // [128][KSTR] (also Q staging)
    uint32_t* Vs = sm + 128 * KSTR;    // [128][VSTR]

    const int b = blockIdx.z, h = blockIdx.y;
    const int qbase = blockIdx.x * 128;
    const int tid = threadIdx.x;
    const int w = tid >> 5, lane = tid & 31, g = lane >> 2, t = lane & 3;
    const int row = 16 * w + g;

    // ---- stage Q tile, hoist A-fragments to registers ----
    const float* qp = g_q + ((size_t)(b * SEQ + qbase)) * D_MODEL + h * DH;
    for (int i = tid; i < 128 * 12; i += 256) {
        int r = i / 12, c = i % 12;
        float4 v = *(const float4*)(qp + (size_t)r * D_MODEL + c * 4);
        *(uint4*)(Ks + r * KSTR + c * 4) = f4tf(v);
    }
    __syncthreads();
    uint32_t aq[6][4];
    #pragma unroll
    for (int kk = 0; kk < 6; ++kk) {
        aq[kk][0] = Ks[row * KSTR + kk * 8 + t];
        aq[kk][1] = Ks[(row + 8) * KSTR + kk * 8 + t];
        aq[kk][2] = Ks[row * KSTR + kk * 8 + t + 4];
        aq[kk][3] = Ks[(row + 8) * KSTR + kk * 8 + t + 4];
    }

    const float* kp = g_k + (size_t)b * SEQ * D_MODEL + h * DH;
    const float* vp = g_v + (size_t)b * SEQ * D_MODEL + h * DH;

    // ---- pass 1: online softmax stats (log2 domain) ----
    float m0 = -1e30f, m1 = -1e30f, s0 = 0.f, s1 = 0.f;
    for (int ch = 0; ch < 16; ++ch) {
        __syncthreads();
        for (int i = tid; i < 128 * 12; i += 256) {
            int r = i / 12, c = i % 12;
            float4 v = *(const float4*)(kp + (size_t)(ch * 128 + r) * D_MODEL + c * 4);
            *(uint4*)(Ks + r * KSTR + c * 4) = f4tf(v);
        }
        __syncthreads();
        float4 acc[16];
        #pragma unroll
        for (int ns = 0; ns < 16; ++ns) acc[ns] = make_float4(0.f, 0.f, 0.f, 0.f);
        #pragma unroll
        for (int ns = 0; ns < 16; ++ns) {
            #pragma unroll
            for (int kk = 0; kk < 6; ++kk) {
                uint32_t b0 = Ks[(ns * 8 + g) * KSTR + kk * 8 + t];
                uint32_t b1 = Ks[(ns * 8 + g) * KSTR + kk * 8 + t + 4];
                mma_tf32(acc[ns], aq[kk], b0, b1);
            }
        }
        float cm0 = -1e30f, cm1 = -1e30f;
        #pragma unroll
        for (int ns = 0; ns < 16; ++ns) {
            acc[ns].x *= SL2E; acc[ns].y *= SL2E;
            acc[ns].z *= SL2E; acc[ns].w *= SL2E;
            cm0 = fmaxf(cm0, fmaxf(acc[ns].x, acc[ns].y));
            cm1 = fmaxf(cm1, fmaxf(acc[ns].z, acc[ns].w));
        }
        cm0 = fmaxf(cm0, __shfl_xor_sync(0xffffffffu, cm0, 1));
        cm0 = fmaxf(cm0, __shfl_xor_sync(0xffffffffu, cm0, 2));
        cm1 = fmaxf(cm1, __shfl_xor_sync(0xffffffffu, cm1, 1));
        cm1 = fmaxf(cm1, __shfl_xor_sync(0xffffffffu, cm1, 2));
        float nm0 = fmaxf(m0, cm0), nm1 = fmaxf(m1, cm1);
        float e0 = 0.f, e1 = 0.f;
        #pragma unroll
        for (int ns = 0; ns < 16; ++ns) {
            e0 += exp2f(acc[ns].x - nm0) + exp2f(acc[ns].y - nm0);
            e1 += exp2f(acc[ns].z - nm1) + exp2f(acc[ns].w - nm1);
        }
        e0 += __shfl_xor_sync(0xffffffffu, e0, 1);
        e0 += __shfl_xor_sync(0xffffffffu, e0, 2);
        e1 += __shfl_xor_sync(0xffffffffu, e1, 1);
        e1 += __shfl_xor_sync(0xffffffffu, e1, 2);
        s0 = s0 * exp2f(m0 - nm0) + e0;  m0 = nm0;
        s1 = s1 * exp2f(m1 - nm1) + e1;  m1 = nm1;
    }
    const float inv0 = 1.f / s0, inv1 = 1.f / s1;

    // ---- pass 2: recompute, write attn, accumulate context ----
    float* arow = attn + ((size_t)(h * NUM_B + b) * SEQ + qbase) * SEQ;
    const int srcA = (lane & 0x1C) | (t >> 1);
    const int srcB = srcA + 2;
    const bool odd = (t & 1);

    float4 cacc[6];
    #pragma unroll
    for (int n = 0; n < 6; ++n) cacc[n] = make_float4(0.f, 0.f, 0.f, 0.f);

    for (int ch = 0; ch < 16; ++ch) {
        __syncthreads();
        for (int i = tid; i < 128 * 12; i += 256) {
            int r = i / 12, c = i % 12;
            float4 kv = *(const float4*)(kp + (size_t)(ch * 128 + r) * D_MODEL + c * 4);
            *(uint4*)(Ks + r * KSTR + c * 4) = f4tf(kv);
            float4 vv = *(const float4*)(vp + (size_t)(ch * 128 + r) * D_MODEL + c * 4);
            *(uint4*)(Vs + r * VSTR + c * 4) = f4tf(vv);
        }
        __syncthreads();
        float* r0p = arow + (size_t)row * SEQ + ch * 128 + 2 * t;
        float* r1p = r0p + (size_t)8 * SEQ;
        #pragma unroll
        for (int ns = 0; ns < 16; ++ns) {
            float4 sa = make_float4(0.f, 0.f, 0.f, 0.f);
            #pragma unroll
            for (int kk = 0; kk < 6; ++kk) {
                uint32_t b0 = Ks[(ns * 8 + g) * KSTR + kk * 8 + t];
                uint32_t b1 = Ks[(ns * 8 + g) * KSTR + kk * 8 + t + 4];
                mma_tf32(sa, aq[kk], b0, b1);
            }
            float px = exp2f(sa.x * SL2E - m0) * inv0;
            float py = exp2f(sa.y * SL2E - m0) * inv0;
            float pz = exp2f(sa.z * SL2E - m1) * inv1;
            float pw = exp2f(sa.w * SL2E - m1) * inv1;
            *(float2*)(r0p + ns * 8) = make_float2(px, py);
            *(float2*)(r1p + ns * 8) = make_float2(pz, pw);
            // C-frag -> A-frag (P[g][t], P[g+8][t], P[g][t+4], P[g+8][t+4])
            float xA = __shfl_sync(0xffffffffu, px, srcA);
            float yA = __shfl_sync(0xffffffffu, py, srcA);
            float zA = __shfl_sync(0xffffffffu, pz, srcA);
            float wA = __shfl_sync(0xffffffffu, pw, srcA);
            float xB = __shfl_sync(0xffffffffu, px, srcB);
            float yB = __shfl_sync(0xffffffffu, py, srcB);
            float zB = __shfl_sync(0xffffffffu, pz, srcB);
            float wB = __shfl_sync(0xffffffffu, pw, srcB);
            uint32_t pa[4];
            pa[0] = f2tf(odd ? yA : xA);
            pa[1] = f2tf(odd ? wA : zA);
            pa[2] = f2tf(odd ? yB : xB);
            pa[3] = f2tf(odd ? wB : zB);
            #pragma unroll
            for (int n = 0; n < 6; ++n) {
                uint32_t b0 = Vs[(ns * 8 + t) * VSTR + n * 8 + g];
                uint32_t b1 = Vs[(ns * 8 + t + 4) * VSTR + n * 8 + g];
                mma_tf32(cacc[n], pa, b0, b1);
            }
        }
    }

    float* cp  = ctx + ((size_t)(b * SEQ + qbase + row)) * D_MODEL + h * DH + 2 * t;
    float* cp2 = cp + (size_t)8 * D_MODEL;
    #pragma unroll
    for (int n = 0; n < 6; ++n) {
        *(float2*)(cp  + n * 8) = make_float2(cacc[n].x, cacc[n].y);
        *(float2*)(cp2 + n * 8) = make_float2(cacc[n].z, cacc[n].w);
    }
}

// ---------------- launch -------------------------------------
extern "C" void kernel_launch(void* const* d_in, const int* in_sizes, int n_in,
                              void* d_out, int out_size)
{
    const float* query = (const float*)d_in[0];
    const float* key   = (const float*)d_in[1];
    const float* value = (const float*)d_in[2];
    const float* Wq    = (const float*)d_in[3];
    const float* bq    = (const float*)d_in[4];
    const float* Wk    = (const float*)d_in[5];
    const float* bk    = (const float*)d_in[6];
    const float* Wv    = (const float*)d_in[7];
    const float* bv    = (const float*)d_in[8];

    float* out  = (float*)d_out;
    float* ctx  = out;                                   // (B, S, 384)
    float* attn = out + (size_t)MROWS * D_MODEL;         // (H*B, S, S)

    void* pq = nullptr; void* pk = nullptr; void* pv = nullptr;
    cudaGetSymbolAddress(&pq, g_q);
    cudaGetSymbolAddress(&pk, g_k);
    cudaGetSymbolAddress(&pv, g_v);

    cudaFuncSetAttribute(fused_attn, cudaFuncAttributeMaxDynamicSharedMemorySize, FUSED_SMEM);

    dim3 pgrid(D_MODEL / 128, MROWS / 128);              // (3, 128)
    proj_tc<<<pgrid, 256>>>(query, Wq, bq, (float*)pq);
    proj_tc<<<pgrid, 256>>>(key,   Wk, bk, (float*)pk);
    proj_tc<<<pgrid, 256>>>(value, Wv, bv, (float*)pv);

    dim3 agrid(SEQ / 128, NUM_H, NUM_B);                 // (16, 8, 8)
    fused_attn<<<agrid, 256, FUSED_SMEM>>>(ctx, attn);
}